// round 10
// baseline (speedup 1.0000x reference)
#include <cuda_runtime.h>
#include <cuda_fp16.h>
#include <cstdint>

// ============================================================
// WeightOnlyInt8Linear: out = input @ weight^T * scales
// R10: persistent-CTA fp16 GEMM.
//   - 304 CTAs (2/SM), each walks ~7 tiles; cp.async pipeline
//     runs CONTINUOUSLY across tile boundaries (one fill per CTA,
//     not per tile); epilogue overlaps next tile's loads.
//   - R6 inner loop (direct LDS->MMA; reg pipeline dropped to
//     free registers), CTA 128x128x64, 3-stage, warp 64x32.
//   - GROUPM 8 raster (R6/R8 best), fused pack pre-pass.
// ncu R9: tensor=71.5%, nothing else near roof -> idle was
// startup/epilogue/tail; this removes them.
// ============================================================

static constexpr int MDIM = 8192;
static constexpr int NDIM = 4096;
static constexpr int KDIM = 4096;

static constexpr int BM = 128;
static constexpr int BN = 128;
static constexpr int BK = 64;             // 4 k16 steps
static constexpr int NKT = KDIM / BK;     // 32 per tile
static constexpr int NTILES = (MDIM / BM) * (NDIM / BN);   // 2048

static constexpr int A_ST_BYTES = (BM / 16) * (BK / 16) * 512;   // 16384
static constexpr int B_ST_BYTES = (BN / 8) * (BK / 16) * 256;    // 16384
static constexpr int STAGE_BYTES = A_ST_BYTES + B_ST_BYTES;      // 32768
static constexpr int SMEM_BYTES = 3 * STAGE_BYTES;               // 98304

// static scratch: fragment-major fp16
__device__ __half g_af[(size_t)MDIM * KDIM];   // 64 MB: [m16-tile][k16-tile][512B]
__device__ __half g_wf[(size_t)NDIM * KDIM];   // 32 MB: [n8-tile][k16-tile][256B]

// ---------------- helpers ----------------
__device__ __forceinline__ uint32_t smem_u32(const void* p) {
    uint32_t a;
    asm("{ .reg .u64 t; cvta.to.shared.u64 t, %1; cvt.u32.u64 %0, t; }"
        : "=r"(a) : "l"(p));
    return a;
}
__device__ __forceinline__ void cp_async16(uint32_t dst, const void* src) {
    asm volatile("cp.async.cg.shared.global [%0], [%1], 16;"
                 :: "r"(dst), "l"(src) : "memory");
}
#define CP_COMMIT() asm volatile("cp.async.commit_group;" ::: "memory")
#define CP_WAIT(n)  asm volatile("cp.async.wait_group %0;" :: "n"(n) : "memory")

#define MMA_F16(d, a0, a1, a2, a3, b0, b1)                                    \
    asm volatile("mma.sync.aligned.m16n8k16.row.col.f32.f16.f16.f32 "         \
                 "{%0,%1,%2,%3}, {%4,%5,%6,%7}, {%8,%9}, {%0,%1,%2,%3};"      \
                 : "+f"((d)[0]), "+f"((d)[1]), "+f"((d)[2]), "+f"((d)[3])     \
                 : "r"(a0), "r"(a1), "r"(a2), "r"(a3), "r"(b0), "r"(b1))

// ---------------- fused pack kernel (A & W interleaved) ----------------
__global__ void __launch_bounds__(256) pack_fused_kernel(
    const float* __restrict__ a, const int* __restrict__ w)
{
    const int bid  = blockIdx.x;
    const int role = bid & 1;
    const int idx  = bid >> 1;

    if (role == 0) {
        const int rt = idx >> 3;
        const int k0 = (idx & 7) * 512;
        __shared__ __half sh[16][520];

        #pragma unroll
        for (int u = threadIdx.x; u < 2048; u += 256) {
            const int row = u >> 7, c4 = u & 127;
            float4 v = *reinterpret_cast<const float4*>(
                a + (size_t)(rt * 16 + row) * KDIM + k0 + c4 * 4);
            __half2* d = reinterpret_cast<__half2*>(&sh[row][c4 * 4]);
            d[0] = __floats2half2_rn(v.x, v.y);
            d[1] = __floats2half2_rn(v.z, v.w);
        }
        __syncthreads();

        #pragma unroll
        for (int u = threadIdx.x; u < 1024; u += 256) {
            const int kt = u >> 5, lane = u & 31;
            const int g = lane >> 2, t = lane & 3;
            const int kc = kt * 16 + 2 * t;
            uint32_t r0 = *reinterpret_cast<const uint32_t*>(&sh[g][kc]);
            uint32_t r1 = *reinterpret_cast<const uint32_t*>(&sh[g + 8][kc]);
            uint32_t r2 = *reinterpret_cast<const uint32_t*>(&sh[g][kc + 8]);
            uint32_t r3 = *reinterpret_cast<const uint32_t*>(&sh[g + 8][kc + 8]);
            int4* dst = reinterpret_cast<int4*>(
                reinterpret_cast<char*>(g_af)
                + (((size_t)rt * 256 + (k0 >> 4) + kt) << 9) + lane * 16);
            *dst = make_int4(r0, r1, r2, r3);
        }
    } else {
        const int nt = idx >> 3;
        const int k0 = (idx & 7) * 512;
        __shared__ __half shw[8][520];

        #pragma unroll
        for (int u = threadIdx.x; u < 1024; u += 256) {
            const int row = u >> 7, c4 = u & 127;
            int4 v = *reinterpret_cast<const int4*>(
                w + (size_t)(nt * 8 + row) * KDIM + k0 + c4 * 4);
            __half2* d = reinterpret_cast<__half2*>(&shw[row][c4 * 4]);
            d[0] = __floats2half2_rn((float)v.x, (float)v.y);
            d[1] = __floats2half2_rn((float)v.z, (float)v.w);
        }
        __syncthreads();

        #pragma unroll
        for (int u = threadIdx.x; u < 1024; u += 256) {
            const int kt = u >> 5, lane = u & 31;
            const int g = lane >> 2, t = lane & 3;
            const int kc = kt * 16 + 2 * t;
            uint32_t b0 = *reinterpret_cast<const uint32_t*>(&shw[g][kc]);
            uint32_t b1 = *reinterpret_cast<const uint32_t*>(&shw[g][kc + 8]);
            int2* dst = reinterpret_cast<int2*>(
                reinterpret_cast<char*>(g_wf)
                + (((size_t)nt * 256 + (k0 >> 4) + kt) << 8) + lane * 8);
            *dst = make_int2(b0, b1);
        }
    }
}

// tile index -> fragment-tile base coords (GROUPM=8 raster, num_n=32)
__device__ __forceinline__ void tile_coords(int tile, int& rt0, int& nt0) {
    const int grp = tile >> 8;          // / (8*32)
    const int rem = tile & 255;
    rt0 = (grp * 8 + (rem & 7)) * 8;    // mtile * (BM/16)
    nt0 = (rem >> 3) * 16;              // ntile * (BN/8)
}

// ---------------- main GEMM (persistent) ----------------
__global__ void __launch_bounds__(256, 2) gemm_kernel(
    const float* __restrict__ scales, float* __restrict__ out)
{
    extern __shared__ char smem[];
    const uint32_t sbase = smem_u32(smem);

    const int tid  = threadIdx.x;
    const int lane = tid & 31;
    const int wid  = tid >> 5;
    const int wm   = wid >> 2;        // 0..1
    const int wn   = wid & 3;         // 0..3
    const int g    = lane >> 2;
    const int t    = lane & 3;
    const int stride = gridDim.x;     // persistent stride (304)

    const char* gA = reinterpret_cast<const char*>(g_af);
    const char* gB = reinterpret_cast<const char*>(g_wf);

    float acc[4][4][4];
    #pragma unroll
    for (int i = 0; i < 4; i++)
        #pragma unroll
        for (int j = 0; j < 4; j++)
            #pragma unroll
            for (int c = 0; c < 4; c++) acc[i][j][c] = 0.0f;

    #define ISSUE_STAGE(rt_, nt_, kt_, slot_)                                  \
    do {                                                                       \
        const int _kt4 = (kt_) * 4;                                            \
        const uint32_t _sa = sbase + (uint32_t)(slot_) * STAGE_BYTES;          \
        const uint32_t _sb = _sa + A_ST_BYTES;                                 \
        _Pragma("unroll")                                                      \
        for (int u = tid; u < 1024; u += 256) {        /* A: 16KB */           \
            const int mi = u >> 7;                                             \
            cp_async16(_sa + (u << 4),                                         \
                gA + (((size_t)((rt_) + mi) * 256 + _kt4) << 9)                \
                   + ((u & 127) << 4));                                        \
        }                                                                      \
        _Pragma("unroll")                                                      \
        for (int u = tid; u < 1024; u += 256) {        /* B: 16KB */           \
            const int nj = u >> 6;                                             \
            cp_async16(_sb + (u << 4),                                         \
                gB + (((size_t)((nt_) + nj) * 256 + _kt4) << 8)                \
                   + ((u & 63) << 4));                                         \
        }                                                                      \
    } while (0)

    int tile = blockIdx.x;
    int rt0, nt0, rt0n, nt0n;
    tile_coords(tile, rt0, nt0);
    {
        const int tn = tile + stride;
        if (tn < NTILES) tile_coords(tn, rt0n, nt0n);
        else { rt0n = rt0; nt0n = nt0; }
    }

    // one-time pipeline fill
    ISSUE_STAGE(rt0, nt0, 0, 0); CP_COMMIT();
    ISSUE_STAGE(rt0, nt0, 1, 1); CP_COMMIT();

    int s_cur = 0, s_nxt = 2;
    const uint32_t lane16 = (uint32_t)lane * 16;
    const uint32_t lane8  = (uint32_t)lane * 8;
    const uint32_t a_warp = (uint32_t)(wm * 4) * 2048;
    const uint32_t b_warp = (uint32_t)(wn * 4) * 1024;

    for (; tile < NTILES; tile += stride) {
        const bool has_next = (tile + stride) < NTILES;

        #pragma unroll 1
        for (int kt = 0; kt < NKT; kt++) {
            CP_WAIT(1);
            __syncthreads();

            // prefetch iteration kt+2 (crosses into next tile at 30/31)
            const int kn = kt + 2;
            if (kn < NKT) {
                ISSUE_STAGE(rt0, nt0, kn, s_nxt);
            } else if (has_next) {
                ISSUE_STAGE(rt0n, nt0n, kn - NKT, s_nxt);
            }
            CP_COMMIT();

            const uint32_t sa = sbase + (uint32_t)s_cur * STAGE_BYTES;
            const uint32_t sb = sa + A_ST_BYTES;

            #pragma unroll
            for (int ks = 0; ks < 4; ks++) {
                uint32_t bf[4][2];
                #pragma unroll
                for (int j = 0; j < 4; j++) {
                    const uint32_t addr =
                        sb + b_warp + (uint32_t)((j * 4 + ks) * 256) + lane8;
                    asm volatile("ld.shared.v2.u32 {%0,%1}, [%2];"
                                 : "=r"(bf[j][0]), "=r"(bf[j][1]) : "r"(addr));
                }
                #pragma unroll
                for (int i = 0; i < 4; i++) {
                    uint32_t a0, a1, a2, a3;
                    const uint32_t addr =
                        sa + a_warp + (uint32_t)((i * 4 + ks) * 512) + lane16;
                    asm volatile("ld.shared.v4.u32 {%0,%1,%2,%3}, [%4];"
                                 : "=r"(a0), "=r"(a1), "=r"(a2), "=r"(a3) : "r"(addr));
                    #pragma unroll
                    for (int j = 0; j < 4; j++)
                        MMA_F16(acc[i][j], a0, a1, a2, a3, bf[j][0], bf[j][1]);
                }
            }

            s_cur = (s_cur == 2) ? 0 : s_cur + 1;
            s_nxt = (s_nxt == 2) ? 0 : s_nxt + 1;
        }

        // ---- epilogue for this tile (next tile's loads already in flight) ----
        const int m0 = (rt0 >> 3) * BM;
        const int n0 = (nt0 >> 4) * BN;
        const int orow0 = m0 + wm * 64;
        const int ocol0 = n0 + wn * 32;
        #pragma unroll
        for (int j = 0; j < 4; j++) {
            const int col = ocol0 + j * 8 + 2 * t;
            const float2 sc = *reinterpret_cast<const float2*>(scales + col);
            #pragma unroll
            for (int i = 0; i < 4; i++) {
                const int row = orow0 + i * 16 + g;
                float2 v0 = { acc[i][j][0] * sc.x, acc[i][j][1] * sc.y };
                float2 v1 = { acc[i][j][2] * sc.x, acc[i][j][3] * sc.y };
                *reinterpret_cast<float2*>(out + (size_t)row * NDIM + col)       = v0;
                *reinterpret_cast<float2*>(out + (size_t)(row + 8) * NDIM + col) = v1;
                acc[i][j][0] = 0.0f; acc[i][j][1] = 0.0f;
                acc[i][j][2] = 0.0f; acc[i][j][3] = 0.0f;
            }
        }

        // rotate tile coords
        rt0 = rt0n; nt0 = nt0n;
        const int tnn = tile + 2 * stride;
        if (tnn < NTILES) tile_coords(tnn, rt0n, nt0n);
    }
}

// ---------------- host ----------------
extern "C" void kernel_launch(void* const* d_in, const int* in_sizes, int n_in,
                              void* d_out, int out_size) {
    const float* input  = (const float*)d_in[0];
    const int*   weight = (const int*)d_in[1];
    const float* scales = (const float*)d_in[2];
    float* out = (float*)d_out;

    pack_fused_kernel<<<8192, 256>>>(input, weight);

    cudaFuncSetAttribute(gemm_kernel,
                         cudaFuncAttributeMaxDynamicSharedMemorySize, SMEM_BYTES);

    int dev = 0, nsm = 148;
    cudaGetDevice(&dev);
    cudaDeviceGetAttribute(&nsm, cudaDevAttrMultiProcessorCount, dev);
    const int grid = 2 * nsm;          // persistent: 2 CTAs per SM
    gemm_kernel<<<grid, 256, SMEM_BYTES>>>(scales, out);
}

// round 11
// speedup vs baseline: 1.0785x; 1.0785x over previous
#include <cuda_runtime.h>
#include <cuda_fp16.h>
#include <cstdint>

// ============================================================
// WeightOnlyInt8Linear: out = input @ weight^T * scales
// R11: warp tile 64x64 at occupancy 2 via 128-thread CTAs.
//   CTA 128x128x64, 4 warps (each 64x64), 2 CTA/SM ->
//   256 regs/thread available (acc=128 fits, no spill).
//   A-frag reuse x8 (was x4): smem bytes 224 -> 160 B/mma,
//   per-SM crossbar 256->192 KB/ktile — relieves the
//   tensor(71%)/L1(58%) co-contention seen in R9/R10 ncu.
//   3-stage cp.async, fused pack pre-pass, GROUPM 8 raster.
// ============================================================

static constexpr int MDIM = 8192;
static constexpr int NDIM = 4096;
static constexpr int KDIM = 4096;

static constexpr int BM = 128;
static constexpr int BN = 128;
static constexpr int BK = 64;             // 4 k16 steps
static constexpr int STAGES = 3;
static constexpr int NKT = KDIM / BK;     // 64

static constexpr int A_ST_BYTES = (BM / 16) * (BK / 16) * 512;   // 16384
static constexpr int B_ST_BYTES = (BN / 8) * (BK / 16) * 256;    // 16384
static constexpr int STAGE_BYTES = A_ST_BYTES + B_ST_BYTES;      // 32768
static constexpr int SMEM_BYTES = STAGES * STAGE_BYTES;          // 98304

// static scratch: fragment-major fp16
__device__ __half g_af[(size_t)MDIM * KDIM];   // 64 MB: [m16-tile][k16-tile][512B]
__device__ __half g_wf[(size_t)NDIM * KDIM];   // 32 MB: [n8-tile][k16-tile][256B]

// ---------------- helpers ----------------
__device__ __forceinline__ uint32_t smem_u32(const void* p) {
    uint32_t a;
    asm("{ .reg .u64 t; cvta.to.shared.u64 t, %1; cvt.u32.u64 %0, t; }"
        : "=r"(a) : "l"(p));
    return a;
}
__device__ __forceinline__ void cp_async16(uint32_t dst, const void* src) {
    asm volatile("cp.async.cg.shared.global [%0], [%1], 16;"
                 :: "r"(dst), "l"(src) : "memory");
}
#define CP_COMMIT() asm volatile("cp.async.commit_group;" ::: "memory")
#define CP_WAIT(n)  asm volatile("cp.async.wait_group %0;" :: "n"(n) : "memory")

#define MMA_F16(d, a0, a1, a2, a3, b0, b1)                                    \
    asm volatile("mma.sync.aligned.m16n8k16.row.col.f32.f16.f16.f32 "         \
                 "{%0,%1,%2,%3}, {%4,%5,%6,%7}, {%8,%9}, {%0,%1,%2,%3};"      \
                 : "+f"((d)[0]), "+f"((d)[1]), "+f"((d)[2]), "+f"((d)[3])     \
                 : "r"(a0), "r"(a1), "r"(a2), "r"(a3), "r"(b0), "r"(b1))

// ---------------- fused pack kernel (A & W interleaved) ----------------
__global__ void __launch_bounds__(256) pack_fused_kernel(
    const float* __restrict__ a, const int* __restrict__ w)
{
    const int bid  = blockIdx.x;
    const int role = bid & 1;
    const int idx  = bid >> 1;

    if (role == 0) {
        const int rt = idx >> 3;
        const int k0 = (idx & 7) * 512;
        __shared__ __half sh[16][520];

        #pragma unroll
        for (int u = threadIdx.x; u < 2048; u += 256) {
            const int row = u >> 7, c4 = u & 127;
            float4 v = *reinterpret_cast<const float4*>(
                a + (size_t)(rt * 16 + row) * KDIM + k0 + c4 * 4);
            __half2* d = reinterpret_cast<__half2*>(&sh[row][c4 * 4]);
            d[0] = __floats2half2_rn(v.x, v.y);
            d[1] = __floats2half2_rn(v.z, v.w);
        }
        __syncthreads();

        #pragma unroll
        for (int u = threadIdx.x; u < 1024; u += 256) {
            const int kt = u >> 5, lane = u & 31;
            const int g = lane >> 2, t = lane & 3;
            const int kc = kt * 16 + 2 * t;
            uint32_t r0 = *reinterpret_cast<const uint32_t*>(&sh[g][kc]);
            uint32_t r1 = *reinterpret_cast<const uint32_t*>(&sh[g + 8][kc]);
            uint32_t r2 = *reinterpret_cast<const uint32_t*>(&sh[g][kc + 8]);
            uint32_t r3 = *reinterpret_cast<const uint32_t*>(&sh[g + 8][kc + 8]);
            int4* dst = reinterpret_cast<int4*>(
                reinterpret_cast<char*>(g_af)
                + (((size_t)rt * 256 + (k0 >> 4) + kt) << 9) + lane * 16);
            *dst = make_int4(r0, r1, r2, r3);
        }
    } else {
        const int nt = idx >> 3;
        const int k0 = (idx & 7) * 512;
        __shared__ __half shw[8][520];

        #pragma unroll
        for (int u = threadIdx.x; u < 1024; u += 256) {
            const int row = u >> 7, c4 = u & 127;
            int4 v = *reinterpret_cast<const int4*>(
                w + (size_t)(nt * 8 + row) * KDIM + k0 + c4 * 4);
            __half2* d = reinterpret_cast<__half2*>(&shw[row][c4 * 4]);
            d[0] = __floats2half2_rn((float)v.x, (float)v.y);
            d[1] = __floats2half2_rn((float)v.z, (float)v.w);
        }
        __syncthreads();

        #pragma unroll
        for (int u = threadIdx.x; u < 1024; u += 256) {
            const int kt = u >> 5, lane = u & 31;
            const int g = lane >> 2, t = lane & 3;
            const int kc = kt * 16 + 2 * t;
            uint32_t b0 = *reinterpret_cast<const uint32_t*>(&shw[g][kc]);
            uint32_t b1 = *reinterpret_cast<const uint32_t*>(&shw[g][kc + 8]);
            int2* dst = reinterpret_cast<int2*>(
                reinterpret_cast<char*>(g_wf)
                + (((size_t)nt * 256 + (k0 >> 4) + kt) << 8) + lane * 8);
            *dst = make_int2(b0, b1);
        }
    }
}

// ---------------- main GEMM: 128 threads, 4 warps of 64x64 ----------------
__global__ void __launch_bounds__(128, 2) gemm_kernel(
    const float* __restrict__ scales, float* __restrict__ out)
{
    extern __shared__ char smem[];
    const uint32_t sbase = smem_u32(smem);

    const int tid  = threadIdx.x;
    const int lane = tid & 31;
    const int wid  = tid >> 5;        // 0..3
    const int wm   = wid >> 1;        // 0..1 (64-row slab)
    const int wn   = wid & 1;         // 0..1 (64-col slab)
    const int g    = lane >> 2;
    const int t    = lane & 3;

    // grouped-M raster (GROUPM=8, num_n=32)
    const int num_n  = NDIM / BN;     // 32
    const int GROUPM = 8;
    const int bid = blockIdx.x;
    const int grp = bid / (GROUPM * num_n);
    const int rem = bid % (GROUPM * num_n);
    const int m0 = (grp * GROUPM + (rem % GROUPM)) * BM;
    const int n0 = (rem / GROUPM) * BN;
    const int rt0 = m0 >> 4;
    const int nt0 = n0 >> 3;

    float acc[4][8][4];               // 128 regs: warp tile 64x64
    #pragma unroll
    for (int i = 0; i < 4; i++)
        #pragma unroll
        for (int j = 0; j < 8; j++)
            #pragma unroll
            for (int c = 0; c < 4; c++) acc[i][j][c] = 0.0f;

    const char* gA = reinterpret_cast<const char*>(g_af);
    const char* gB = reinterpret_cast<const char*>(g_wf);

    #define ISSUE_STAGE(kt_, slot_)                                            \
    do {                                                                       \
        const int _kt4 = (kt_) * 4;                                            \
        const uint32_t _sa = sbase + (uint32_t)(slot_) * STAGE_BYTES;          \
        const uint32_t _sb = _sa + A_ST_BYTES;                                 \
        _Pragma("unroll")                                                      \
        for (int u = tid; u < 1024; u += 128) {        /* A: 16KB */           \
            const int mi = u >> 7;                                             \
            cp_async16(_sa + (u << 4),                                         \
                gA + (((size_t)(rt0 + mi) * 256 + _kt4) << 9)                  \
                   + ((u & 127) << 4));                                        \
        }                                                                      \
        _Pragma("unroll")                                                      \
        for (int u = tid; u < 1024; u += 128) {        /* B: 16KB */           \
            const int nj = u >> 6;                                             \
            cp_async16(_sb + (u << 4),                                         \
                gB + (((size_t)(nt0 + nj) * 256 + _kt4) << 8)                  \
                   + ((u & 63) << 4));                                         \
        }                                                                      \
    } while (0)

    ISSUE_STAGE(0, 0); CP_COMMIT();
    ISSUE_STAGE(1, 1); CP_COMMIT();

    int s_cur = 0, s_nxt = 2;
    const uint32_t lane16 = (uint32_t)lane * 16;
    const uint32_t lane8  = (uint32_t)lane * 8;
    const uint32_t a_warp = (uint32_t)(wm * 4) * 2048;   // (wm*4+i)*4ks*512
    const uint32_t b_warp = (uint32_t)(wn * 8) * 1024;   // (wn*8+j)*4ks*256

    for (int kt = 0; kt < NKT; kt++) {
        CP_WAIT(1);
        __syncthreads();

        const int kn = kt + 2;
        if (kn < NKT) ISSUE_STAGE(kn, s_nxt);
        CP_COMMIT();

        const uint32_t sa = sbase + (uint32_t)s_cur * STAGE_BYTES;
        const uint32_t sb = sa + A_ST_BYTES;

        #pragma unroll
        for (int ks = 0; ks < 4; ks++) {
            uint32_t bf[8][2];
            #pragma unroll
            for (int j = 0; j < 8; j++) {
                const uint32_t addr =
                    sb + b_warp + (uint32_t)((j * 4 + ks) * 256) + lane8;
                asm volatile("ld.shared.v2.u32 {%0,%1}, [%2];"
                             : "=r"(bf[j][0]), "=r"(bf[j][1]) : "r"(addr));
            }
            #pragma unroll
            for (int i = 0; i < 4; i++) {
                uint32_t a0, a1, a2, a3;
                const uint32_t addr =
                    sa + a_warp + (uint32_t)((i * 4 + ks) * 512) + lane16;
                asm volatile("ld.shared.v4.u32 {%0,%1,%2,%3}, [%4];"
                             : "=r"(a0), "=r"(a1), "=r"(a2), "=r"(a3) : "r"(addr));
                #pragma unroll
                for (int j = 0; j < 8; j++)
                    MMA_F16(acc[i][j], a0, a1, a2, a3, bf[j][0], bf[j][1]);
            }
        }

        s_cur = (s_cur == 2) ? 0 : s_cur + 1;
        s_nxt = (s_nxt == 2) ? 0 : s_nxt + 1;
    }

    // ---- epilogue: scale and store ----
    const int orow0 = m0 + wm * 64;
    const int ocol0 = n0 + wn * 64;
    #pragma unroll
    for (int j = 0; j < 8; j++) {
        const int col = ocol0 + j * 8 + 2 * t;
        const float2 sc = *reinterpret_cast<const float2*>(scales + col);
        #pragma unroll
        for (int i = 0; i < 4; i++) {
            const int row = orow0 + i * 16 + g;
            float2 v0 = { acc[i][j][0] * sc.x, acc[i][j][1] * sc.y };
            float2 v1 = { acc[i][j][2] * sc.x, acc[i][j][3] * sc.y };
            *reinterpret_cast<float2*>(out + (size_t)row * NDIM + col)       = v0;
            *reinterpret_cast<float2*>(out + (size_t)(row + 8) * NDIM + col) = v1;
        }
    }
}

// ---------------- host ----------------
extern "C" void kernel_launch(void* const* d_in, const int* in_sizes, int n_in,
                              void* d_out, int out_size) {
    const float* input  = (const float*)d_in[0];
    const int*   weight = (const int*)d_in[1];
    const float* scales = (const float*)d_in[2];
    float* out = (float*)d_out;

    pack_fused_kernel<<<8192, 256>>>(input, weight);

    cudaFuncSetAttribute(gemm_kernel,
                         cudaFuncAttributeMaxDynamicSharedMemorySize, SMEM_BYTES);
    const int grid = (MDIM / BM) * (NDIM / BN);   // 2048
    gemm_kernel<<<grid, 128, SMEM_BYTES>>>(scales, out);
}

// round 12
// speedup vs baseline: 1.1285x; 1.0463x over previous
#include <cuda_runtime.h>
#include <cuda_fp16.h>
#include <cstdint>

// ============================================================
// WeightOnlyInt8Linear: out = input @ weight^T * scales
// R12: R11 (warp 64x64, 128-thr CTA, occ 2, CTA 128x128x64,
// 3-stage cp.async) + issue-stream smoothing:
//   (1) cp.async prefetch split into 4 chunks, one before each
//       ks block (no post-barrier LSU burst / mio_throttle);
//   (2) B fragments PAIRED in memory: one LDS.128 = 2 ks of B
//       (B LDS issues halved; bytes unchanged).
// ============================================================

static constexpr int MDIM = 8192;
static constexpr int NDIM = 4096;
static constexpr int KDIM = 4096;

static constexpr int BM = 128;
static constexpr int BN = 128;
static constexpr int BK = 64;             // 4 k16 steps
static constexpr int NKT = KDIM / BK;     // 64

static constexpr int A_ST_BYTES = (BM / 16) * (BK / 16) * 512;   // 16384
static constexpr int B_ST_BYTES = (BN / 8) * (BK / 16) * 256;    // 16384
static constexpr int STAGE_BYTES = A_ST_BYTES + B_ST_BYTES;      // 32768
static constexpr int SMEM_BYTES = 3 * STAGE_BYTES;               // 98304

// static scratch (fragment-major fp16)
__device__ __half g_af[(size_t)MDIM * KDIM];   // 64 MB: [m16][k16][512B]
__device__ __half g_wf[(size_t)NDIM * KDIM];   // 32 MB: [n8][k16-PAIR][512B: lane*16 + (k16&1)*8]

// ---------------- helpers ----------------
__device__ __forceinline__ uint32_t smem_u32(const void* p) {
    uint32_t a;
    asm("{ .reg .u64 t; cvta.to.shared.u64 t, %1; cvt.u32.u64 %0, t; }"
        : "=r"(a) : "l"(p));
    return a;
}
__device__ __forceinline__ void cp_async16(uint32_t dst, const void* src) {
    asm volatile("cp.async.cg.shared.global [%0], [%1], 16;"
                 :: "r"(dst), "l"(src) : "memory");
}
#define CP_COMMIT() asm volatile("cp.async.commit_group;" ::: "memory")
#define CP_WAIT(n)  asm volatile("cp.async.wait_group %0;" :: "n"(n) : "memory")

#define MMA_F16(d, a0, a1, a2, a3, b0, b1)                                    \
    asm volatile("mma.sync.aligned.m16n8k16.row.col.f32.f16.f16.f32 "         \
                 "{%0,%1,%2,%3}, {%4,%5,%6,%7}, {%8,%9}, {%0,%1,%2,%3};"      \
                 : "+f"((d)[0]), "+f"((d)[1]), "+f"((d)[2]), "+f"((d)[3])     \
                 : "r"(a0), "r"(a1), "r"(a2), "r"(a3), "r"(b0), "r"(b1))

// ---------------- fused pack kernel ----------------
__global__ void __launch_bounds__(256) pack_fused_kernel(
    const float* __restrict__ a, const int* __restrict__ w)
{
    const int bid  = blockIdx.x;
    const int role = bid & 1;
    const int idx  = bid >> 1;

    if (role == 0) {
        // ---- A pack: f32 -> f16 fragment-major ----
        const int rt = idx >> 3;
        const int k0 = (idx & 7) * 512;
        __shared__ __half sh[16][520];

        #pragma unroll
        for (int u = threadIdx.x; u < 2048; u += 256) {
            const int row = u >> 7, c4 = u & 127;
            float4 v = *reinterpret_cast<const float4*>(
                a + (size_t)(rt * 16 + row) * KDIM + k0 + c4 * 4);
            __half2* d = reinterpret_cast<__half2*>(&sh[row][c4 * 4]);
            d[0] = __floats2half2_rn(v.x, v.y);
            d[1] = __floats2half2_rn(v.z, v.w);
        }
        __syncthreads();

        #pragma unroll
        for (int u = threadIdx.x; u < 1024; u += 256) {
            const int kt = u >> 5, lane = u & 31;
            const int g = lane >> 2, t = lane & 3;
            const int kc = kt * 16 + 2 * t;
            uint32_t r0 = *reinterpret_cast<const uint32_t*>(&sh[g][kc]);
            uint32_t r1 = *reinterpret_cast<const uint32_t*>(&sh[g + 8][kc]);
            uint32_t r2 = *reinterpret_cast<const uint32_t*>(&sh[g][kc + 8]);
            uint32_t r3 = *reinterpret_cast<const uint32_t*>(&sh[g + 8][kc + 8]);
            int4* dst = reinterpret_cast<int4*>(
                reinterpret_cast<char*>(g_af)
                + (((size_t)rt * 256 + (k0 >> 4) + kt) << 9) + lane * 16);
            *dst = make_int4(r0, r1, r2, r3);
        }
    } else {
        // ---- W pack: int32 -> f16, PAIRED fragment-major ----
        const int nt = idx >> 3;
        const int k0 = (idx & 7) * 512;
        __shared__ __half shw[8][520];

        #pragma unroll
        for (int u = threadIdx.x; u < 1024; u += 256) {
            const int row = u >> 7, c4 = u & 127;
            int4 v = *reinterpret_cast<const int4*>(
                w + (size_t)(nt * 8 + row) * KDIM + k0 + c4 * 4);
            __half2* d = reinterpret_cast<__half2*>(&shw[row][c4 * 4]);
            d[0] = __floats2half2_rn((float)v.x, (float)v.y);
            d[1] = __floats2half2_rn((float)v.z, (float)v.w);
        }
        __syncthreads();

        #pragma unroll
        for (int u = threadIdx.x; u < 1024; u += 256) {
            const int kt = u >> 5, lane = u & 31;
            const int g = lane >> 2, t = lane & 3;
            const int kc = kt * 16 + 2 * t;
            uint32_t b0 = *reinterpret_cast<const uint32_t*>(&shw[g][kc]);
            uint32_t b1 = *reinterpret_cast<const uint32_t*>(&shw[g][kc + 8]);
            const int ktg = (k0 >> 4) + kt;      // global k16 index 0..255
            int2* dst = reinterpret_cast<int2*>(
                reinterpret_cast<char*>(g_wf)
                + (((size_t)nt * 128 + (ktg >> 1)) << 9)
                + lane * 16 + (ktg & 1) * 8);
            *dst = make_int2(b0, b1);
        }
    }
}

// ---------------- main GEMM: 128 threads, 4 warps of 64x64 ----------------
__global__ void __launch_bounds__(128, 2) gemm_kernel(
    const float* __restrict__ scales, float* __restrict__ out)
{
    extern __shared__ char smem[];
    const uint32_t sbase = smem_u32(smem);

    const int tid  = threadIdx.x;
    const int lane = tid & 31;
    const int wid  = tid >> 5;        // 0..3
    const int wm   = wid >> 1;        // 0..1
    const int wn   = wid & 1;         // 0..1
    const int g    = lane >> 2;
    const int t    = lane & 3;

    // grouped-M raster (GROUPM=8, num_n=32)
    const int num_n  = NDIM / BN;
    const int GROUPM = 8;
    const int bid = blockIdx.x;
    const int grp = bid / (GROUPM * num_n);
    const int rem = bid % (GROUPM * num_n);
    const int m0 = (grp * GROUPM + (rem % GROUPM)) * BM;
    const int n0 = (rem / GROUPM) * BN;
    const int rt0 = m0 >> 4;
    const int nt0 = n0 >> 3;

    float acc[4][8][4];
    #pragma unroll
    for (int i = 0; i < 4; i++)
        #pragma unroll
        for (int j = 0; j < 8; j++)
            #pragma unroll
            for (int c = 0; c < 4; c++) acc[i][j][c] = 0.0f;

    const char* gA = reinterpret_cast<const char*>(g_af);
    const char* gB = reinterpret_cast<const char*>(g_wf);

    // full-stage issue (prologue): A [mi(8)][ks(4)][512B], B [nj(16)][1024B]
    #define ISSUE_STAGE(kt_, slot_)                                            \
    do {                                                                       \
        const int _kt4 = (kt_) * 4;                                            \
        const uint32_t _sa = sbase + (uint32_t)(slot_) * STAGE_BYTES;          \
        const uint32_t _sb = _sa + A_ST_BYTES;                                 \
        _Pragma("unroll")                                                      \
        for (int u = tid; u < 1024; u += 128) {                                \
            const int mi = u >> 7;                                             \
            cp_async16(_sa + (u << 4),                                         \
                gA + (((size_t)(rt0 + mi) * 256 + _kt4) << 9)                  \
                   + ((u & 127) << 4));                                        \
        }                                                                      \
        _Pragma("unroll")                                                      \
        for (int u = tid; u < 1024; u += 128) {                                \
            const int nj = u >> 6;                                             \
            cp_async16(_sb + (u << 4),                                         \
                gB + (((size_t)(nt0 + nj) * 128 + (kt_) * 2) << 9)             \
                   + ((u & 63) << 4));                                         \
        }                                                                      \
    } while (0)

    // quarter-stage issue chunk c (0,1: A halves; 2,3: B halves)
    #define ISSUE_CHUNK(kt_, slot_, c_)                                        \
    do {                                                                       \
        const int _kt4 = (kt_) * 4;                                            \
        const uint32_t _sa = sbase + (uint32_t)(slot_) * STAGE_BYTES;          \
        const uint32_t _sb = _sa + A_ST_BYTES;                                 \
        if ((c_) < 2) {                                                        \
            _Pragma("unroll")                                                  \
            for (int q = 0; q < 4; q++) {                                      \
                const int u = tid + ((c_) * 4 + q) * 128;                      \
                const int mi = u >> 7;                                         \
                cp_async16(_sa + (u << 4),                                     \
                    gA + (((size_t)(rt0 + mi) * 256 + _kt4) << 9)              \
                       + ((u & 127) << 4));                                    \
            }                                                                  \
        } else {                                                               \
            _Pragma("unroll")                                                  \
            for (int q = 0; q < 4; q++) {                                      \
                const int u = tid + (((c_) - 2) * 4 + q) * 128;                \
                const int nj = u >> 6;                                         \
                cp_async16(_sb + (u << 4),                                     \
                    gB + (((size_t)(nt0 + nj) * 128 + (kt_) * 2) << 9)         \
                       + ((u & 63) << 4));                                     \
            }                                                                  \
        }                                                                      \
    } while (0)

    ISSUE_STAGE(0, 0); CP_COMMIT();
    ISSUE_STAGE(1, 1); CP_COMMIT();

    int s_cur = 0, s_nxt = 2;
    const uint32_t lane16 = (uint32_t)lane * 16;
    const uint32_t a_warp = (uint32_t)(wm * 4) * 2048;   // (wm*4+i)*4ks*512
    const uint32_t b_warp = (uint32_t)(wn * 8) * 1024;   // (wn*8+j)*1024

    for (int kt = 0; kt < NKT; kt++) {
        CP_WAIT(1);
        __syncthreads();

        const int kn = kt + 2;
        const bool pre = (kn < NKT);
        const uint32_t sa = sbase + (uint32_t)s_cur * STAGE_BYTES;
        const uint32_t sb = sa + A_ST_BYTES;

        uint32_t bf[8][4];    // B pair buffer: [j][ {ks even: r0,r1} {ks odd: r2,r3} ]

        #pragma unroll
        for (int ks = 0; ks < 4; ks++) {
            if (pre) ISSUE_CHUNK(kn, s_nxt, ks);

            const int h = ks & 1;
            if (h == 0) {
                const int p = ks >> 1;
                #pragma unroll
                for (int j = 0; j < 8; j++) {
                    const uint32_t addr =
                        sb + b_warp + (uint32_t)(j * 1024 + p * 512) + lane16;
                    asm volatile("ld.shared.v4.u32 {%0,%1,%2,%3}, [%4];"
                                 : "=r"(bf[j][0]), "=r"(bf[j][1]),
                                   "=r"(bf[j][2]), "=r"(bf[j][3]) : "r"(addr));
                }
            }
            #pragma unroll
            for (int i = 0; i < 4; i++) {
                uint32_t a0, a1, a2, a3;
                const uint32_t addr =
                    sa + a_warp + (uint32_t)((i * 4 + ks) * 512) + lane16;
                asm volatile("ld.shared.v4.u32 {%0,%1,%2,%3}, [%4];"
                             : "=r"(a0), "=r"(a1), "=r"(a2), "=r"(a3) : "r"(addr));
                #pragma unroll
                for (int j = 0; j < 8; j++)
                    MMA_F16(acc[i][j], a0, a1, a2, a3,
                            bf[j][h * 2], bf[j][h * 2 + 1]);
            }
        }
        CP_COMMIT();

        s_cur = (s_cur == 2) ? 0 : s_cur + 1;
        s_nxt = (s_nxt == 2) ? 0 : s_nxt + 1;
    }

    // ---- epilogue: scale and store ----
    const int orow0 = m0 + wm * 64;
    const int ocol0 = n0 + wn * 64;
    #pragma unroll
    for (int j = 0; j < 8; j++) {
        const int col = ocol0 + j * 8 + 2 * t;
        const float2 sc = *reinterpret_cast<const float2*>(scales + col);
        #pragma unroll
        for (int i = 0; i < 4; i++) {
            const int row = orow0 + i * 16 + g;
            float2 v0 = { acc[i][j][0] * sc.x, acc[i][j][1] * sc.y };
            float2 v1 = { acc[i][j][2] * sc.x, acc[i][j][3] * sc.y };
            *reinterpret_cast<float2*>(out + (size_t)row * NDIM + col)       = v0;
            *reinterpret_cast<float2*>(out + (size_t)(row + 8) * NDIM + col) = v1;
        }
    }
}

// ---------------- host ----------------
extern "C" void kernel_launch(void* const* d_in, const int* in_sizes, int n_in,
                              void* d_out, int out_size) {
    const float* input  = (const float*)d_in[0];
    const int*   weight = (const int*)d_in[1];
    const float* scales = (const float*)d_in[2];
    float* out = (float*)d_out;

    pack_fused_kernel<<<8192, 256>>>(input, weight);

    cudaFuncSetAttribute(gemm_kernel,
                         cudaFuncAttributeMaxDynamicSharedMemorySize, SMEM_BYTES);
    const int grid = (MDIM / BM) * (NDIM / BN);   // 2048
    gemm_kernel<<<grid, 128, SMEM_BYTES>>>(scales, out);
}